// round 6
// baseline (speedup 1.0000x reference)
#include <cuda_runtime.h>
#include <cuda_bf16.h>
#include <cstdint>

#define BB   1024
#define TT   256
#define CC   384
#define HS   64

// Pre-split scratch (device globals: allocation-free).
__device__ __align__(16) __nv_bfloat16 QhG[BB * TT * HS], QlG[BB * TT * HS];
__device__ __align__(16) __nv_bfloat16 KhG[BB * TT * HS], KlG[BB * TT * HS];
__device__ __align__(16) __nv_bfloat16 VthG[BB * HS * TT], VtlG[BB * HS * TT]; // [b][hs][t]
__device__ __align__(16) __nv_bfloat16 WbH[192 * 384], WbL[192 * 384];         // [n][k]

// ---------------- helpers ----------------
__device__ __forceinline__ uint32_t smem_u32(const void* p) {
    uint32_t a;
    asm("{ .reg .u64 t; cvta.to.shared.u64 t, %1; cvt.u32.u64 %0, t; }" : "=r"(a) : "l"(p));
    return a;
}
__device__ __forceinline__ void cp16(uint32_t dst, const void* src) {
    asm volatile("cp.async.ca.shared.global [%0], [%1], 16;" :: "r"(dst), "l"(src) : "memory");
}
#define CP_COMMIT() asm volatile("cp.async.commit_group;" ::: "memory")
#define CP_WAIT1()  asm volatile("cp.async.wait_group 1;" ::: "memory")
#define CP_WAIT0()  asm volatile("cp.async.wait_group 0;" ::: "memory")

#define LDM_X4(r0, r1, r2, r3, a)                                            \
    asm volatile("ldmatrix.sync.aligned.m8n8.x4.shared.b16 {%0,%1,%2,%3}, [%4];" \
                 : "=r"(r0), "=r"(r1), "=r"(r2), "=r"(r3) : "r"(a))

// fp32 pair -> packed bf16 hi / lo pair.
__device__ __forceinline__ void split2(float a, float b, uint32_t& h, uint32_t& l) {
    __nv_bfloat162 hh = __floats2bfloat162_rn(a, b);
    float ra = a - __bfloat162float(hh.x);
    float rb = b - __bfloat162float(hh.y);
    __nv_bfloat162 ll = __floats2bfloat162_rn(ra, rb);
    h = *reinterpret_cast<uint32_t*>(&hh);
    l = *reinterpret_cast<uint32_t*>(&ll);
}

// exp2(x) for x <= 0, FMA pipe only.
__device__ __forceinline__ float fexp2f(float x) {
    x = fmaxf(x, -125.0f);
    float fi = floorf(x);
    float f = x - fi;
    float p = 0.0018775767f;
    p = fmaf(p, f, 0.0089893397f);
    p = fmaf(p, f, 0.055826318f);
    p = fmaf(p, f, 0.24015361f);
    p = fmaf(p, f, 0.69315308f);
    p = fmaf(p, f, 1.0f);
    return p * __int_as_float(((int)fi + 127) << 23);
}
#define SCALE2 0.18033688f   // 0.125 * log2(e)

__device__ __forceinline__ void mma16816(float* c,
                                         const uint32_t* a,
                                         uint32_t b0, uint32_t b1) {
    asm volatile(
        "mma.sync.aligned.m16n8k16.row.col.f32.bf16.bf16.f32 "
        "{%0,%1,%2,%3}, {%4,%5,%6,%7}, {%8,%9}, {%0,%1,%2,%3};"
        : "+f"(c[0]), "+f"(c[1]), "+f"(c[2]), "+f"(c[3])
        : "r"(a[0]), "r"(a[1]), "r"(a[2]), "r"(a[3]), "r"(b0), "r"(b1));
}

// ============================================================================
// Kernel 0: split W into bf16 hi/lo at layout [n][k].
// ============================================================================
__global__ void prep_w(const float* __restrict__ Wq,
                       const float* __restrict__ Wk,
                       const float* __restrict__ Wv)
{
    int idx = blockIdx.x * blockDim.x + threadIdx.x;
    if (idx >= 192 * 384) return;
    int n = idx / 384;
    int k = idx % 384;
    int m = n >> 6, hs = n & 63;
    const float* W = (m == 0) ? Wq : ((m == 1) ? Wk : Wv);
    float v = W[k * HS + hs];
    __nv_bfloat16 h = __float2bfloat16(v);
    __nv_bfloat16 l = __float2bfloat16(v - __bfloat162float(h));
    WbH[n * 384 + k] = h;
    WbL[n * 384 + k] = l;
}

// ============================================================================
// Kernel 1: QKV projection. A split at staging (register pipeline), all
// fragment loads via ldmatrix.x4. Single-buffered smem, 2 syncs/chunk.
// Grid 2048, 256 thr. CTA tile 128(M) x 192(N); warps 4m x 2n (32x96).
// ============================================================================
#define AST 40                       // smem stride (halves) for A and B tiles
#define AH_OFF 0
#define AL_OFF 10240
#define BH_OFF 20480
#define BL_OFF 35840
#define QKV_SMEM 51200

__global__ __launch_bounds__(256, 1)
void qkv_mma(const float* __restrict__ X)
{
    extern __shared__ char sm[];
    const uint32_t sb = smem_u32(sm);
    const int tid  = threadIdx.x;
    const int lane = tid & 31;
    const int w    = tid >> 5;
    const int m0   = (w >> 1) * 32;
    const int n0   = (w & 1) * 96;
    const int gid  = lane >> 2;
    const int tg   = lane & 3;
    const int l15  = lane & 15;
    const int lh8  = (lane >> 4) << 3;
    const size_t row0 = (size_t)blockIdx.x * 128;

    // per-lane ldmatrix fragment base offsets (bytes)
    const uint32_t aFrag = (uint32_t)((m0 + l15) * AST + lh8) * 2;
    const uint32_t bFrag = (uint32_t)((n0 + l15) * AST + lh8) * 2;

    float4 xr[4];
    uint4  br[6];

    auto ldg = [&](int c) {
        const int k0 = c * 32;
#pragma unroll
        for (int it = 0; it < 4; it++) {
            int i = tid + 256 * it;
            xr[it] = *reinterpret_cast<const float4*>(
                &X[(row0 + (i >> 3)) * CC + k0 + ((i & 7) << 2)]);
        }
#pragma unroll
        for (int it = 0; it < 6; it++) {
            int i = tid + 256 * it;
            bool hi = (i < 768);
            int rem = hi ? i : i - 768;
            const __nv_bfloat16* src = hi ? WbH : WbL;
            br[it] = *reinterpret_cast<const uint4*>(
                &src[(rem >> 2) * 384 + k0 + ((rem & 3) << 3)]);
        }
    };

    auto sts = [&]() {
        __nv_bfloat16* AhP = reinterpret_cast<__nv_bfloat16*>(sm + AH_OFF);
        __nv_bfloat16* AlP = reinterpret_cast<__nv_bfloat16*>(sm + AL_OFF);
#pragma unroll
        for (int it = 0; it < 4; it++) {
            int i = tid + 256 * it;
            int r = i >> 3, c4 = (i & 7) << 2;
            uint32_t h0, l0, h1, l1;
            split2(xr[it].x, xr[it].y, h0, l0);
            split2(xr[it].z, xr[it].w, h1, l1);
            *reinterpret_cast<uint2*>(&AhP[r * AST + c4]) = make_uint2(h0, h1);
            *reinterpret_cast<uint2*>(&AlP[r * AST + c4]) = make_uint2(l0, l1);
        }
#pragma unroll
        for (int it = 0; it < 6; it++) {
            int i = tid + 256 * it;
            bool hi = (i < 768);
            int rem = hi ? i : i - 768;
            int r = rem >> 2, c8 = (rem & 3) << 3;
            char* base = sm + (hi ? BH_OFF : BL_OFF);
            *reinterpret_cast<uint4*>(base + (uint32_t)(r * AST + c8) * 2) = br[it];
        }
    };

    float acc[2][12][4] = {};

    ldg(0);
#pragma unroll 1
    for (int c = 0; c < 12; c++) {
        sts();
        __syncthreads();
        if (c < 11) ldg(c + 1);

#pragma unroll
        for (int kk = 0; kk < 32; kk += 16) {
            uint32_t ah[2][4], al[2][4];
#pragma unroll
            for (int mt = 0; mt < 2; mt++) {
                const uint32_t o = aFrag + (uint32_t)(mt * 16 * AST + kk) * 2;
                LDM_X4(ah[mt][0], ah[mt][1], ah[mt][2], ah[mt][3], sb + AH_OFF + o);
                LDM_X4(al[mt][0], al[mt][1], al[mt][2], al[mt][3], sb + AL_OFF + o);
            }
#pragma unroll
            for (int p = 0; p < 6; p++) {
                const uint32_t o = bFrag + (uint32_t)(p * 16 * AST + kk) * 2;
                uint32_t h0, h1, h2, h3, L0, L1, L2, L3;
                LDM_X4(h0, h1, h2, h3, sb + BH_OFF + o);
                LDM_X4(L0, L1, L2, L3, sb + BL_OFF + o);
#pragma unroll
                for (int mt = 0; mt < 2; mt++) {
                    float* c0 = acc[mt][2 * p];
                    mma16816(c0, ah[mt], h0, h2);
                    mma16816(c0, ah[mt], L0, L2);
                    mma16816(c0, al[mt], h0, h2);
                    float* c1 = acc[mt][2 * p + 1];
                    mma16816(c1, ah[mt], h1, h3);
                    mma16816(c1, ah[mt], L1, L3);
                    mma16816(c1, al[mt], h1, h3);
                }
            }
        }
        __syncthreads();
    }

    // --- epilogue: split to bf16 hi/lo, store Q/K row-major, V transposed ---
#pragma unroll
    for (int nt = 0; nt < 12; nt++) {
        const int colg = n0 + nt * 8 + 2 * tg;
        const int mat  = colg >> 6;
        const int hs0  = colg & 63;
#pragma unroll
        for (int mt = 0; mt < 2; mt++) {
            const size_t rowA = row0 + m0 + mt * 16 + gid;
            const size_t rowB = rowA + 8;
            const float* cc = acc[mt][nt];
            if (mat == 2) {
                const size_t baseA = (rowA >> 8) * (size_t)(HS * TT) + (rowA & 255);
                const size_t baseB = (rowB >> 8) * (size_t)(HS * TT) + (rowB & 255);
#pragma unroll
                for (int e = 0; e < 4; e++) {
                    const float v = cc[e];
                    __nv_bfloat16 h = __float2bfloat16(v);
                    __nv_bfloat16 l = __float2bfloat16(v - __bfloat162float(h));
                    const size_t base = (e < 2) ? baseA : baseB;
                    const size_t off  = base + (size_t)(hs0 + (e & 1)) * TT;
                    VthG[off] = h;
                    VtlG[off] = l;
                }
            } else {
                __nv_bfloat16* dh = (mat == 0) ? QhG : KhG;
                __nv_bfloat16* dl = (mat == 0) ? QlG : KlG;
                uint32_t h, l;
                split2(cc[0], cc[1], h, l);
                *reinterpret_cast<uint32_t*>(&dh[rowA * HS + hs0]) = h;
                *reinterpret_cast<uint32_t*>(&dl[rowA * HS + hs0]) = l;
                split2(cc[2], cc[3], h, l);
                *reinterpret_cast<uint32_t*>(&dh[rowB * HS + hs0]) = h;
                *reinterpret_cast<uint32_t*>(&dl[rowB * HS + hs0]) = l;
            }
        }
    }
}

// ============================================================================
// Kernel 2: FA2 attention, ldmatrix fragment loads, cp.async double-buffered
// 64-key chunks. Grid (2, 1024), 256 thr = 8 warps x 16 query rows.
// ============================================================================
#define KP 72
#define ABUF 36864                      // Kh|Kl|Vh|Vl, each 64*KP*2 = 9216 B
#define ATTN_SMEM (2 * ABUF)            // 73728

__global__ __launch_bounds__(256, 1)
void attn_mma(float* __restrict__ out)
{
    extern __shared__ char sm[];
    const uint32_t sb = smem_u32(sm);
    const int half = blockIdx.x;
    const int b    = blockIdx.y;
    const int tid  = threadIdx.x;
    const int lane = tid & 31;
    const int w    = tid >> 5;
    const int gid  = lane >> 2;
    const int tg   = lane & 3;
    const int l15  = lane & 15;
    const int lh8  = (lane >> 4) << 3;
    const int qb   = half * 128 + w * 16;

    const uint32_t fOff = (uint32_t)(l15 * KP + lh8) * 2;   // per-lane ldmatrix offset

    auto stage = [&](int c, int buf) {
        const int kn0 = c * 64;
#pragma unroll
        for (int it = 0; it < 8; it++) {
            int i   = tid + 256 * it;     // 0..2047
            int arr = i >> 9;              // 0..3
            int rem = i & 511;
            int r   = rem >> 3;
            int c8  = (rem & 7) << 3;
            uint32_t dst = sb + buf * ABUF + arr * 9216 + (uint32_t)(r * KP + c8) * 2;
            const __nv_bfloat16* src;
            if (arr == 0)      src = &KhG[((size_t)b * TT + kn0 + r) * HS + c8];
            else if (arr == 1) src = &KlG[((size_t)b * TT + kn0 + r) * HS + c8];
            else if (arr == 2) src = &VthG[((size_t)b * HS + r) * TT + kn0 + c8];
            else               src = &VtlG[((size_t)b * HS + r) * TT + kn0 + c8];
            cp16(dst, src);
        }
        CP_COMMIT();
    };

    // Q fragments direct from pre-split global.
    uint32_t qh[4][4], ql[4][4];
    {
        const size_t r0 = (size_t)b * TT + qb + gid;
#pragma unroll
        for (int ks = 0; ks < 4; ks++) {
            const int o = ks * 16 + 2 * tg;
            qh[ks][0] = *reinterpret_cast<const uint32_t*>(&QhG[r0 * HS + o]);
            qh[ks][1] = *reinterpret_cast<const uint32_t*>(&QhG[(r0 + 8) * HS + o]);
            qh[ks][2] = *reinterpret_cast<const uint32_t*>(&QhG[r0 * HS + o + 8]);
            qh[ks][3] = *reinterpret_cast<const uint32_t*>(&QhG[(r0 + 8) * HS + o + 8]);
            ql[ks][0] = *reinterpret_cast<const uint32_t*>(&QlG[r0 * HS + o]);
            ql[ks][1] = *reinterpret_cast<const uint32_t*>(&QlG[(r0 + 8) * HS + o]);
            ql[ks][2] = *reinterpret_cast<const uint32_t*>(&QlG[r0 * HS + o + 8]);
            ql[ks][3] = *reinterpret_cast<const uint32_t*>(&QlG[(r0 + 8) * HS + o + 8]);
        }
    }

    float O[32];
#pragma unroll
    for (int i = 0; i < 32; i++) O[i] = 0.f;
    float mr0 = -1e30f, mr1 = -1e30f, l0 = 0.f, l1 = 0.f;

    const int nch = (half + 1) * 2;
    stage(0, 0);
#pragma unroll 1
    for (int c = 0; c < nch; c++) {
        if (c < nch - 1) { stage(c + 1, (c + 1) & 1); CP_WAIT1(); } else { CP_WAIT0(); }
        __syncthreads();
        const int kn0 = c * 64;
        const uint32_t kbase = sb + (c & 1) * ABUF;

        if (kn0 <= qb) {
            // ---- scores ----
            float s[32];
#pragma unroll
            for (int i = 0; i < 32; i++) s[i] = 0.f;
#pragma unroll
            for (int ks = 0; ks < 4; ks++) {
#pragma unroll
                for (int p = 0; p < 4; p++) {
                    const uint32_t o = fOff + (uint32_t)(p * 16 * KP + ks * 16) * 2;
                    uint32_t h0, h1, h2, h3, L0, L1, L2, L3;
                    LDM_X4(h0, h1, h2, h3, kbase + o);
                    LDM_X4(L0, L1, L2, L3, kbase + 9216 + o);
                    float* c0 = &s[(2 * p) * 4];
                    float* c1 = &s[(2 * p + 1) * 4];
                    mma16816(c0, qh[ks], h0, h2);
                    mma16816(c0, qh[ks], L0, L2);
                    mma16816(c0, ql[ks], h0, h2);
                    mma16816(c1, qh[ks], h1, h3);
                    mma16816(c1, qh[ks], L1, L3);
                    mma16816(c1, ql[ks], h1, h3);
                }
            }
#pragma unroll
            for (int i = 0; i < 32; i++) s[i] *= SCALE2;

            if (kn0 + 63 > qb) {
                const int r0 = qb + gid, r1 = qb + 8 + gid;
#pragma unroll
                for (int nt = 0; nt < 8; nt++) {
                    const int col = kn0 + nt * 8 + 2 * tg;
                    if (col     > r0) s[nt * 4 + 0] = -1e30f;
                    if (col + 1 > r0) s[nt * 4 + 1] = -1e30f;
                    if (col     > r1) s[nt * 4 + 2] = -1e30f;
                    if (col + 1 > r1) s[nt * 4 + 3] = -1e30f;
                }
            }
            // ---- online softmax (base-2) ----
            float c0m = -1e30f, c1m = -1e30f;
#pragma unroll
            for (int nt = 0; nt < 8; nt++) {
                c0m = fmaxf(c0m, fmaxf(s[nt * 4 + 0], s[nt * 4 + 1]));
                c1m = fmaxf(c1m, fmaxf(s[nt * 4 + 2], s[nt * 4 + 3]));
            }
            c0m = fmaxf(c0m, __shfl_xor_sync(0xffffffffu, c0m, 1));
            c0m = fmaxf(c0m, __shfl_xor_sync(0xffffffffu, c0m, 2));
            c1m = fmaxf(c1m, __shfl_xor_sync(0xffffffffu, c1m, 1));
            c1m = fmaxf(c1m, __shfl_xor_sync(0xffffffffu, c1m, 2));
            const float mn0 = fmaxf(mr0, c0m), mn1 = fmaxf(mr1, c1m);
            const float corr0 = fexp2f(mr0 - mn0), corr1 = fexp2f(mr1 - mn1);
            mr0 = mn0; mr1 = mn1;

            float sum0 = 0.f, sum1 = 0.f;
#pragma unroll
            for (int nt = 0; nt < 8; nt++) {
                float p0 = fexp2f(s[nt * 4 + 0] - mn0);
                float p1 = fexp2f(s[nt * 4 + 1] - mn0);
                float p2 = fexp2f(s[nt * 4 + 2] - mn1);
                float p3 = fexp2f(s[nt * 4 + 3] - mn1);
                s[nt * 4 + 0] = p0; s[nt * 4 + 1] = p1;
                s[nt * 4 + 2] = p2; s[nt * 4 + 3] = p3;
                sum0 += p0 + p1; sum1 += p2 + p3;
            }
            sum0 += __shfl_xor_sync(0xffffffffu, sum0, 1);
            sum0 += __shfl_xor_sync(0xffffffffu, sum0, 2);
            sum1 += __shfl_xor_sync(0xffffffffu, sum1, 1);
            sum1 += __shfl_xor_sync(0xffffffffu, sum1, 2);
            l0 = l0 * corr0 + sum0;
            l1 = l1 * corr1 + sum1;
#pragma unroll
            for (int hn = 0; hn < 8; hn++) {
                O[hn * 4 + 0] *= corr0; O[hn * 4 + 1] *= corr0;
                O[hn * 4 + 2] *= corr1; O[hn * 4 + 3] *= corr1;
            }
            // ---- PV ----
#pragma unroll
            for (int ks = 0; ks < 4; ks++) {
                uint32_t ph[4], pl[4];
                split2(s[(2 * ks) * 4 + 0],     s[(2 * ks) * 4 + 1],     ph[0], pl[0]);
                split2(s[(2 * ks) * 4 + 2],     s[(2 * ks) * 4 + 3],     ph[1], pl[1]);
                split2(s[(2 * ks + 1) * 4 + 0], s[(2 * ks + 1) * 4 + 1], ph[2], pl[2]);
                split2(s[(2 * ks + 1) * 4 + 2], s[(2 * ks + 1) * 4 + 3], ph[3], pl[3]);
#pragma unroll
                for (int p = 0; p < 4; p++) {
                    const uint32_t o = fOff + (uint32_t)(p * 16 * KP + ks * 16) * 2;
                    uint32_t h0, h1, h2, h3, L0, L1, L2, L3;
                    LDM_X4(h0, h1, h2, h3, kbase + 18432 + o);
                    LDM_X4(L0, L1, L2, L3, kbase + 27648 + o);
                    float* o0 = &O[(2 * p) * 4];
                    float* o1 = &O[(2 * p + 1) * 4];
                    mma16816(o0, ph, h0, h2);
                    mma16816(o0, pl, h0, h2);
                    mma16816(o0, ph, L0, L2);
                    mma16816(o1, ph, h1, h3);
                    mma16816(o1, pl, h1, h3);
                    mma16816(o1, ph, L1, L3);
                }
            }
        }
        __syncthreads();
    }

    const float i0 = 1.f / l0, i1 = 1.f / l1;
    float* o0 = out + ((size_t)b * TT + qb + gid) * HS;
    float* o1 = o0 + 8 * HS;
#pragma unroll
    for (int hn = 0; hn < 8; hn++) {
        *reinterpret_cast<float2*>(&o0[hn * 8 + 2 * tg]) =
            make_float2(O[hn * 4 + 0] * i0, O[hn * 4 + 1] * i0);
        *reinterpret_cast<float2*>(&o1[hn * 8 + 2 * tg]) =
            make_float2(O[hn * 4 + 2] * i1, O[hn * 4 + 3] * i1);
    }
}

// ============================================================================
extern "C" void kernel_launch(void* const* d_in, const int* in_sizes, int n_in,
                              void* d_out, int out_size)
{
    const float* x  = (const float*)d_in[0];
    const float* Wq = (const float*)d_in[1];
    const float* Wk = (const float*)d_in[2];
    const float* Wv = (const float*)d_in[3];
    float* out = (float*)d_out;

    (void)in_sizes; (void)n_in; (void)out_size;

    prep_w<<<(192 * 384 + 255) / 256, 256>>>(Wq, Wk, Wv);

    cudaFuncSetAttribute(qkv_mma, cudaFuncAttributeMaxDynamicSharedMemorySize, QKV_SMEM);
    qkv_mma<<<2048, 256, QKV_SMEM>>>(x);

    cudaFuncSetAttribute(attn_mma, cudaFuncAttributeMaxDynamicSharedMemorySize, ATTN_SMEM);
    dim3 agrid(2, BB);
    attn_mma<<<agrid, 256, ATTN_SMEM>>>(out);
}

// round 7
// speedup vs baseline: 1.2623x; 1.2623x over previous
#include <cuda_runtime.h>
#include <cuda_bf16.h>
#include <cstdint>

#define BB   1024
#define TT   256
#define CC   384
#define HS   64

// Pre-split scratch for attention (device globals: allocation-free).
__device__ __align__(16) __nv_bfloat16 QhG[BB * TT * HS], QlG[BB * TT * HS];
__device__ __align__(16) __nv_bfloat16 KhG[BB * TT * HS], KlG[BB * TT * HS];
__device__ __align__(16) __nv_bfloat16 VthG[BB * HS * TT], VtlG[BB * HS * TT]; // [b][hs][t]
__device__ __align__(16) float WallG[384 * 192];   // W concat, layout [k][n]

// ---------------- helpers ----------------
__device__ __forceinline__ uint32_t smem_u32(const void* p) {
    uint32_t a;
    asm("{ .reg .u64 t; cvta.to.shared.u64 t, %1; cvt.u32.u64 %0, t; }" : "=r"(a) : "l"(p));
    return a;
}
__device__ __forceinline__ void cp16(uint32_t dst, const void* src) {
    asm volatile("cp.async.ca.shared.global [%0], [%1], 16;" :: "r"(dst), "l"(src) : "memory");
}
#define CP_COMMIT() asm volatile("cp.async.commit_group;" ::: "memory")
#define CP_WAIT1()  asm volatile("cp.async.wait_group 1;" ::: "memory")
#define CP_WAIT0()  asm volatile("cp.async.wait_group 0;" ::: "memory")

// fp32 pair -> packed bf16 hi / lo pair.
__device__ __forceinline__ void split2(float a, float b, uint32_t& h, uint32_t& l) {
    __nv_bfloat162 hh = __floats2bfloat162_rn(a, b);
    float ra = a - __bfloat162float(hh.x);
    float rb = b - __bfloat162float(hh.y);
    __nv_bfloat162 ll = __floats2bfloat162_rn(ra, rb);
    h = *reinterpret_cast<uint32_t*>(&hh);
    l = *reinterpret_cast<uint32_t*>(&ll);
}

// exp2(x) for x <= 0, FMA pipe only.
__device__ __forceinline__ float fexp2f(float x) {
    x = fmaxf(x, -125.0f);
    float fi = floorf(x);
    float f = x - fi;
    float p = 0.0018775767f;
    p = fmaf(p, f, 0.0089893397f);
    p = fmaf(p, f, 0.055826318f);
    p = fmaf(p, f, 0.24015361f);
    p = fmaf(p, f, 0.69315308f);
    p = fmaf(p, f, 1.0f);
    return p * __int_as_float(((int)fi + 127) << 23);
}
#define SCALE2 0.18033688f   // 0.125 * log2(e)

// bf16 m16n8k16 MMA
__device__ __forceinline__ void mma16816(float& c0, float& c1, float& c2, float& c3,
                                         uint32_t a0, uint32_t a1, uint32_t a2, uint32_t a3,
                                         uint32_t b0, uint32_t b1) {
    asm volatile(
        "mma.sync.aligned.m16n8k16.row.col.f32.bf16.bf16.f32 "
        "{%0,%1,%2,%3}, {%4,%5,%6,%7}, {%8,%9}, {%0,%1,%2,%3};"
        : "+f"(c0), "+f"(c1), "+f"(c2), "+f"(c3)
        : "r"(a0), "r"(a1), "r"(a2), "r"(a3), "r"(b0), "r"(b1));
}

// tf32 m16n8k8 MMA (fp32 bits fed directly; HW uses top 19 bits)
__device__ __forceinline__ void mma16808t(float* c,
                                          uint32_t a0, uint32_t a1, uint32_t a2, uint32_t a3,
                                          uint32_t b0, uint32_t b1) {
    asm volatile(
        "mma.sync.aligned.m16n8k8.row.col.f32.tf32.tf32.f32 "
        "{%0,%1,%2,%3}, {%4,%5,%6,%7}, {%8,%9}, {%0,%1,%2,%3};"
        : "+f"(c[0]), "+f"(c[1]), "+f"(c[2]), "+f"(c[3])
        : "r"(a0), "r"(a1), "r"(a2), "r"(a3), "r"(b0), "r"(b1));
}

// ============================================================================
// Kernel 0: concat W into fp32 [k=384][n=192] (n = mat*64 + hs).
// ============================================================================
__global__ void prep_w(const float* __restrict__ Wq,
                       const float* __restrict__ Wk,
                       const float* __restrict__ Wv)
{
    int idx = blockIdx.x * blockDim.x + threadIdx.x;
    if (idx >= 384 * 192) return;
    int k = idx / 192;
    int n = idx % 192;
    int m = n >> 6, hs = n & 63;
    const float* W = (m == 0) ? Wq : ((m == 1) ? Wk : Wv);
    WallG[idx] = W[k * HS + hs];
}

// ============================================================================
// Kernel 1: QKV projection, 1xTF32 (m16n8k8), cp.async double-buffered.
// Grid 2048, 256 thr. CTA tile 128(M) x 192(N); 8 warps 4m x 2n (32x96).
// Epilogue stores pre-split bf16 Q/K (row-major) and V (transposed).
// ============================================================================
#define ASTRIDE 40                  // A smem stride (floats): banks 8*gid+tg
#define BSTRIDE 200                 // B smem stride (floats): banks 8*tg+gid
#define AOFFB 0                     // A: 128*40*4  = 20480 B
#define BOFFB 20480                 // B: 32*200*4  = 25600 B
#define QBUF  46080
#define QKV_SMEM (2 * QBUF)         // 92160 B

__global__ __launch_bounds__(256, 2)
void qkv_mma(const float* __restrict__ X)
{
    extern __shared__ char sm[];
    const int tid  = threadIdx.x;
    const int lane = tid & 31;
    const int w    = tid >> 5;
    const int m0   = (w >> 1) * 32;
    const int n0   = (w & 1) * 96;
    const int gid  = lane >> 2;
    const int tg   = lane & 3;
    const size_t row0 = (size_t)blockIdx.x * 128;
    const uint32_t sb = smem_u32(sm);

    auto stage = [&](int c, int buf) {
        const int k0 = c * 32;
        const uint32_t base = sb + buf * QBUF;
#pragma unroll
        for (int it = 0; it < 4; it++) {
            int i  = tid + 256 * it;          // 0..1023
            int r  = i >> 3;                   // 0..127
            int c4 = (i & 7) << 2;             // 0..28
            cp16(base + AOFFB + (uint32_t)(r * ASTRIDE + c4) * 4,
                 &X[(row0 + r) * CC + k0 + c4]);
        }
#pragma unroll
        for (int it = 0; it < 6; it++) {
            int i  = tid + 256 * it;          // 0..1535
            int r  = i / 48;                   // 0..31
            int c4 = (i % 48) << 2;            // 0..188
            cp16(base + BOFFB + (uint32_t)(r * BSTRIDE + c4) * 4,
                 &WallG[(size_t)(k0 + r) * 192 + c4]);
        }
        CP_COMMIT();
    };

    float acc[2][12][4] = {};

    stage(0, 0);
#pragma unroll 1
    for (int c = 0; c < 12; c++) {
        if (c < 11) { stage(c + 1, (c + 1) & 1); CP_WAIT1(); } else { CP_WAIT0(); }
        __syncthreads();
        const int buf = c & 1;
        const uint32_t* A = reinterpret_cast<const uint32_t*>(sm + buf * QBUF + AOFFB);
        const uint32_t* B = reinterpret_cast<const uint32_t*>(sm + buf * QBUF + BOFFB);

#pragma unroll
        for (int ks = 0; ks < 4; ks++) {
            const int kc = ks * 8 + tg;
            uint32_t a[2][4];
#pragma unroll
            for (int mt = 0; mt < 2; mt++) {
                const int r = m0 + mt * 16 + gid;
                a[mt][0] = A[r * ASTRIDE + kc];
                a[mt][1] = A[(r + 8) * ASTRIDE + kc];
                a[mt][2] = A[r * ASTRIDE + kc + 4];
                a[mt][3] = A[(r + 8) * ASTRIDE + kc + 4];
            }
#pragma unroll
            for (int nt = 0; nt < 12; nt++) {
                const int col = n0 + nt * 8 + gid;
                uint32_t b0 = B[kc * BSTRIDE + col];
                uint32_t b1 = B[(kc + 4) * BSTRIDE + col];
                mma16808t(acc[0][nt], a[0][0], a[0][1], a[0][2], a[0][3], b0, b1);
                mma16808t(acc[1][nt], a[1][0], a[1][1], a[1][2], a[1][3], b0, b1);
            }
        }
        __syncthreads();
    }

    // --- epilogue: split to bf16 hi/lo, store Q/K row-major, V transposed ---
#pragma unroll
    for (int nt = 0; nt < 12; nt++) {
        const int colg = n0 + nt * 8 + 2 * tg;
        const int mat  = colg >> 6;
        const int hs0  = colg & 63;
#pragma unroll
        for (int mt = 0; mt < 2; mt++) {
            const size_t rowA = row0 + m0 + mt * 16 + gid;
            const size_t rowB = rowA + 8;
            const float* cc = acc[mt][nt];
            if (mat == 2) {
                const size_t baseA = (rowA >> 8) * (size_t)(HS * TT) + (rowA & 255);
                const size_t baseB = (rowB >> 8) * (size_t)(HS * TT) + (rowB & 255);
#pragma unroll
                for (int e = 0; e < 4; e++) {
                    const float v = cc[e];
                    __nv_bfloat16 h = __float2bfloat16(v);
                    __nv_bfloat16 l = __float2bfloat16(v - __bfloat162float(h));
                    const size_t base = (e < 2) ? baseA : baseB;
                    const size_t off  = base + (size_t)(hs0 + (e & 1)) * TT;
                    VthG[off] = h;
                    VtlG[off] = l;
                }
            } else {
                __nv_bfloat16* dh = (mat == 0) ? QhG : KhG;
                __nv_bfloat16* dl = (mat == 0) ? QlG : KlG;
                uint32_t h, l;
                split2(cc[0], cc[1], h, l);
                *reinterpret_cast<uint32_t*>(&dh[rowA * HS + hs0]) = h;
                *reinterpret_cast<uint32_t*>(&dl[rowA * HS + hs0]) = l;
                split2(cc[2], cc[3], h, l);
                *reinterpret_cast<uint32_t*>(&dh[rowB * HS + hs0]) = h;
                *reinterpret_cast<uint32_t*>(&dl[rowB * HS + hs0]) = l;
            }
        }
    }
}

// ============================================================================
// Kernel 2: FA2 attention (3-pass split bf16), cp.async double-buffered
// 64-key chunks. Grid (2, 1024), 256 thr = 8 warps x 16 query rows.
// (Identical to the Round-5 version that ran at the HMMA floor.)
// ============================================================================
#define KP 72
#define ABUF 36864                      // Kh|Kl|Vh|Vl, each 64*KP*2 = 9216 B
#define ATTN_SMEM (2 * ABUF)            // 73728

__global__ __launch_bounds__(256, 1)
void attn_mma(float* __restrict__ out)
{
    extern __shared__ char sm[];
    const uint32_t sb = smem_u32(sm);
    const int half = blockIdx.x;
    const int b    = blockIdx.y;
    const int tid  = threadIdx.x;
    const int lane = tid & 31;
    const int w    = tid >> 5;
    const int gid  = lane >> 2;
    const int tg   = lane & 3;
    const int qb   = half * 128 + w * 16;

    auto stage = [&](int c, int buf) {
        const int kn0 = c * 64;
#pragma unroll
        for (int it = 0; it < 8; it++) {
            int i   = tid + 256 * it;     // 0..2047
            int arr = i >> 9;              // 0..3
            int rem = i & 511;
            int r   = rem >> 3;
            int c8  = (rem & 7) << 3;
            uint32_t dst = sb + buf * ABUF + arr * 9216 + (uint32_t)(r * KP + c8) * 2;
            const __nv_bfloat16* src;
            if (arr == 0)      src = &KhG[((size_t)b * TT + kn0 + r) * HS + c8];
            else if (arr == 1) src = &KlG[((size_t)b * TT + kn0 + r) * HS + c8];
            else if (arr == 2) src = &VthG[((size_t)b * HS + r) * TT + kn0 + c8];
            else               src = &VtlG[((size_t)b * HS + r) * TT + kn0 + c8];
            cp16(dst, src);
        }
        CP_COMMIT();
    };

    // Q fragments direct from pre-split global.
    uint32_t qh[4][4], ql[4][4];
    {
        const size_t r0 = (size_t)b * TT + qb + gid;
#pragma unroll
        for (int ks = 0; ks < 4; ks++) {
            const int o = ks * 16 + 2 * tg;
            qh[ks][0] = *reinterpret_cast<const uint32_t*>(&QhG[r0 * HS + o]);
            qh[ks][1] = *reinterpret_cast<const uint32_t*>(&QhG[(r0 + 8) * HS + o]);
            qh[ks][2] = *reinterpret_cast<const uint32_t*>(&QhG[r0 * HS + o + 8]);
            qh[ks][3] = *reinterpret_cast<const uint32_t*>(&QhG[(r0 + 8) * HS + o + 8]);
            ql[ks][0] = *reinterpret_cast<const uint32_t*>(&QlG[r0 * HS + o]);
            ql[ks][1] = *reinterpret_cast<const uint32_t*>(&QlG[(r0 + 8) * HS + o]);
            ql[ks][2] = *reinterpret_cast<const uint32_t*>(&QlG[r0 * HS + o + 8]);
            ql[ks][3] = *reinterpret_cast<const uint32_t*>(&QlG[(r0 + 8) * HS + o + 8]);
        }
    }

    float O[32];
#pragma unroll
    for (int i = 0; i < 32; i++) O[i] = 0.f;
    float mr0 = -1e30f, mr1 = -1e30f, l0 = 0.f, l1 = 0.f;

    const int nch = (half + 1) * 2;
    stage(0, 0);
#pragma unroll 1
    for (int c = 0; c < nch; c++) {
        if (c < nch - 1) { stage(c + 1, (c + 1) & 1); CP_WAIT1(); } else { CP_WAIT0(); }
        __syncthreads();
        const int kn0 = c * 64;
        const int buf = c & 1;
        const __nv_bfloat16* Khs = reinterpret_cast<const __nv_bfloat16*>(sm + buf * ABUF);
        const __nv_bfloat16* Kls = reinterpret_cast<const __nv_bfloat16*>(sm + buf * ABUF + 9216);
        const __nv_bfloat16* Vhs = reinterpret_cast<const __nv_bfloat16*>(sm + buf * ABUF + 18432);
        const __nv_bfloat16* Vls = reinterpret_cast<const __nv_bfloat16*>(sm + buf * ABUF + 27648);

        if (kn0 <= qb) {
            // ---- scores ----
            float s[32];
#pragma unroll
            for (int nt = 0; nt < 8; nt++) {
                float c0 = 0.f, c1 = 0.f, c2 = 0.f, c3 = 0.f;
                const int bn = nt * 8 + gid;
#pragma unroll
                for (int ks = 0; ks < 4; ks++) {
                    uint32_t bh0 = *reinterpret_cast<const uint32_t*>(&Khs[bn * KP + ks * 16 + 2 * tg]);
                    uint32_t bh1 = *reinterpret_cast<const uint32_t*>(&Khs[bn * KP + ks * 16 + 2 * tg + 8]);
                    uint32_t bl0 = *reinterpret_cast<const uint32_t*>(&Kls[bn * KP + ks * 16 + 2 * tg]);
                    uint32_t bl1 = *reinterpret_cast<const uint32_t*>(&Kls[bn * KP + ks * 16 + 2 * tg + 8]);
                    mma16816(c0, c1, c2, c3, qh[ks][0], qh[ks][1], qh[ks][2], qh[ks][3], bh0, bh1);
                    mma16816(c0, c1, c2, c3, qh[ks][0], qh[ks][1], qh[ks][2], qh[ks][3], bl0, bl1);
                    mma16816(c0, c1, c2, c3, ql[ks][0], ql[ks][1], ql[ks][2], ql[ks][3], bh0, bh1);
                }
                s[nt * 4 + 0] = c0 * SCALE2;
                s[nt * 4 + 1] = c1 * SCALE2;
                s[nt * 4 + 2] = c2 * SCALE2;
                s[nt * 4 + 3] = c3 * SCALE2;
            }
            if (kn0 + 63 > qb) {
                const int r0 = qb + gid, r1 = qb + 8 + gid;
#pragma unroll
                for (int nt = 0; nt < 8; nt++) {
                    const int col = kn0 + nt * 8 + 2 * tg;
                    if (col     > r0) s[nt * 4 + 0] = -1e30f;
                    if (col + 1 > r0) s[nt * 4 + 1] = -1e30f;
                    if (col     > r1) s[nt * 4 + 2] = -1e30f;
                    if (col + 1 > r1) s[nt * 4 + 3] = -1e30f;
                }
            }
            // ---- online softmax (base-2) ----
            float c0m = -1e30f, c1m = -1e30f;
#pragma unroll
            for (int nt = 0; nt < 8; nt++) {
                c0m = fmaxf(c0m, fmaxf(s[nt * 4 + 0], s[nt * 4 + 1]));
                c1m = fmaxf(c1m, fmaxf(s[nt * 4 + 2], s[nt * 4 + 3]));
            }
            c0m = fmaxf(c0m, __shfl_xor_sync(0xffffffffu, c0m, 1));
            c0m = fmaxf(c0m, __shfl_xor_sync(0xffffffffu, c0m, 2));
            c1m = fmaxf(c1m, __shfl_xor_sync(0xffffffffu, c1m, 1));
            c1m = fmaxf(c1m, __shfl_xor_sync(0xffffffffu, c1m, 2));
            const float mn0 = fmaxf(mr0, c0m), mn1 = fmaxf(mr1, c1m);
            const float corr0 = fexp2f(mr0 - mn0), corr1 = fexp2f(mr1 - mn1);
            mr0 = mn0; mr1 = mn1;

            float sum0 = 0.f, sum1 = 0.f;
#pragma unroll
            for (int nt = 0; nt < 8; nt++) {
                float p0 = fexp2f(s[nt * 4 + 0] - mn0);
                float p1 = fexp2f(s[nt * 4 + 1] - mn0);
                float p2 = fexp2f(s[nt * 4 + 2] - mn1);
                float p3 = fexp2f(s[nt * 4 + 3] - mn1);
                s[nt * 4 + 0] = p0; s[nt * 4 + 1] = p1;
                s[nt * 4 + 2] = p2; s[nt * 4 + 3] = p3;
                sum0 += p0 + p1; sum1 += p2 + p3;
            }
            sum0 += __shfl_xor_sync(0xffffffffu, sum0, 1);
            sum0 += __shfl_xor_sync(0xffffffffu, sum0, 2);
            sum1 += __shfl_xor_sync(0xffffffffu, sum1, 1);
            sum1 += __shfl_xor_sync(0xffffffffu, sum1, 2);
            l0 = l0 * corr0 + sum0;
            l1 = l1 * corr1 + sum1;
#pragma unroll
            for (int hn = 0; hn < 8; hn++) {
                O[hn * 4 + 0] *= corr0; O[hn * 4 + 1] *= corr0;
                O[hn * 4 + 2] *= corr1; O[hn * 4 + 3] *= corr1;
            }
            // ---- PV ----
#pragma unroll
            for (int ks = 0; ks < 4; ks++) {
                uint32_t ph[4], pl[4];
                split2(s[(2 * ks) * 4 + 0],     s[(2 * ks) * 4 + 1],     ph[0], pl[0]);
                split2(s[(2 * ks) * 4 + 2],     s[(2 * ks) * 4 + 3],     ph[1], pl[1]);
                split2(s[(2 * ks + 1) * 4 + 0], s[(2 * ks + 1) * 4 + 1], ph[2], pl[2]);
                split2(s[(2 * ks + 1) * 4 + 2], s[(2 * ks + 1) * 4 + 3], ph[3], pl[3]);
#pragma unroll
                for (int hn = 0; hn < 8; hn++) {
                    const int vn = hn * 8 + gid;
                    uint32_t vh0 = *reinterpret_cast<const uint32_t*>(&Vhs[vn * KP + ks * 16 + 2 * tg]);
                    uint32_t vh1 = *reinterpret_cast<const uint32_t*>(&Vhs[vn * KP + ks * 16 + 2 * tg + 8]);
                    uint32_t vl0 = *reinterpret_cast<const uint32_t*>(&Vls[vn * KP + ks * 16 + 2 * tg]);
                    uint32_t vl1 = *reinterpret_cast<const uint32_t*>(&Vls[vn * KP + ks * 16 + 2 * tg + 8]);
                    float* o = &O[hn * 4];
                    mma16816(o[0], o[1], o[2], o[3], ph[0], ph[1], ph[2], ph[3], vh0, vh1);
                    mma16816(o[0], o[1], o[2], o[3], pl[0], pl[1], pl[2], pl[3], vh0, vh1);
                    mma16816(o[0], o[1], o[2], o[3], ph[0], ph[1], ph[2], ph[3], vl0, vl1);
                }
            }
        }
        __syncthreads();
    }

    const float i0 = 1.f / l0, i1 = 1.f / l1;
    float* o0 = out + ((size_t)b * TT + qb + gid) * HS;
    float* o1 = o0 + 8 * HS;
#pragma unroll
    for (int hn = 0; hn < 8; hn++) {
        *reinterpret_cast<float2*>(&o0[hn * 8 + 2 * tg]) =
            make_float2(O[hn * 4 + 0] * i0, O[hn * 4 + 1] * i0);
        *reinterpret_cast<float2*>(&o1[hn * 8 + 2 * tg]) =
            make_float2(O[hn * 4 + 2] * i1, O[hn * 4 + 3] * i1);
    }
}

// ============================================================================
extern "C" void kernel_launch(void* const* d_in, const int* in_sizes, int n_in,
                              void* d_out, int out_size)
{
    const float* x  = (const float*)d_in[0];
    const float* Wq = (const float*)d_in[1];
    const float* Wk = (const float*)d_in[2];
    const float* Wv = (const float*)d_in[3];
    float* out = (float*)d_out;

    (void)in_sizes; (void)n_in; (void)out_size;

    prep_w<<<(384 * 192 + 255) / 256, 256>>>(Wq, Wk, Wv);

    cudaFuncSetAttribute(qkv_mma, cudaFuncAttributeMaxDynamicSharedMemorySize, QKV_SMEM);
    qkv_mma<<<2048, 256, QKV_SMEM>>>(x);

    cudaFuncSetAttribute(attn_mma, cudaFuncAttributeMaxDynamicSharedMemorySize, ATTN_SMEM);
    dim3 agrid(2, BB);
    attn_mma<<<agrid, 256, ATTN_SMEM>>>(out);
}